// round 1
// baseline (speedup 1.0000x reference)
#include <cuda_runtime.h>

#define BATCH  256
#define PART   128
#define ONODES 64
#define INODES 64
#define BT     64      // batch rows per CTA
#define NTHREADS 256

// out[b,p,o] = mx[b,p] + log( sum_i exp(x[b,p,i]-mx) * softmax_i(weight[p,o,:]) )
__global__ __launch_bounds__(NTHREADS)
void sumlayer_kernel(const float* __restrict__ x,
                     const float* __restrict__ weight,
                     float* __restrict__ out) {
    __shared__ float sX[BT][INODES + 1];       // exp(x - mx), row-major, pad 65
    __shared__ float sWT[INODES][ONODES];      // softmax(weight), transposed [i][o]
    __shared__ float sMx[BT];

    const int p   = blockIdx.y;
    const int b0  = blockIdx.x * BT;
    const int tid = threadIdx.x;

    // ---------------- Phase W: softmax of weight[p][o][:] -> sWT[i][o] -------
    {
        const int o = tid >> 2;     // 0..63
        const int j = tid & 3;      // 0..3, handles i in [16j, 16j+16)
        const float4* wrow = reinterpret_cast<const float4*>(
            weight + (p * ONODES + o) * INODES + j * 16);
        float v[16];
        #pragma unroll
        for (int q = 0; q < 4; q++) {
            float4 t = wrow[q];
            v[4*q+0] = t.x; v[4*q+1] = t.y; v[4*q+2] = t.z; v[4*q+3] = t.w;
        }
        float m = v[0];
        #pragma unroll
        for (int q = 1; q < 16; q++) m = fmaxf(m, v[q]);
        m = fmaxf(m, __shfl_xor_sync(0xffffffffu, m, 1));
        m = fmaxf(m, __shfl_xor_sync(0xffffffffu, m, 2));
        float s = 0.0f;
        #pragma unroll
        for (int q = 0; q < 16; q++) { v[q] = __expf(v[q] - m); s += v[q]; }
        s += __shfl_xor_sync(0xffffffffu, s, 1);
        s += __shfl_xor_sync(0xffffffffu, s, 2);
        float inv = __fdividef(1.0f, s);
        #pragma unroll
        for (int q = 0; q < 16; q++) sWT[j * 16 + q][o] = v[q] * inv;
    }

    // ---------------- Phase X: exp(x - rowmax) -> sX[r][i], mx -> sMx[r] -----
    {
        const int r = tid >> 2;     // 0..63
        const int j = tid & 3;
        const float4* xrow = reinterpret_cast<const float4*>(
            x + ((size_t)(b0 + r) * PART + p) * INODES + j * 16);
        float v[16];
        #pragma unroll
        for (int q = 0; q < 4; q++) {
            float4 t = xrow[q];
            v[4*q+0] = t.x; v[4*q+1] = t.y; v[4*q+2] = t.z; v[4*q+3] = t.w;
        }
        float m = v[0];
        #pragma unroll
        for (int q = 1; q < 16; q++) m = fmaxf(m, v[q]);
        m = fmaxf(m, __shfl_xor_sync(0xffffffffu, m, 1));
        m = fmaxf(m, __shfl_xor_sync(0xffffffffu, m, 2));
        #pragma unroll
        for (int q = 0; q < 16; q++) sX[r][j * 16 + q] = __expf(v[q] - m);
        if (j == 0) sMx[r] = m;
    }
    __syncthreads();

    // ---------------- GEMM: acc[r][o] = sum_i sX[r][i] * sWT[i][o] ----------
    const int tx = tid & 15;        // o-group: o = tx*4 + k
    const int ty = tid >> 4;        // r-group: r = ty*4 + j
    float acc[4][4];
    #pragma unroll
    for (int j = 0; j < 4; j++)
        #pragma unroll
        for (int k = 0; k < 4; k++) acc[j][k] = 0.0f;

    const float* xr0 = &sX[ty * 4 + 0][0];
    const float* xr1 = &sX[ty * 4 + 1][0];
    const float* xr2 = &sX[ty * 4 + 2][0];
    const float* xr3 = &sX[ty * 4 + 3][0];

    #pragma unroll 16
    for (int i = 0; i < INODES; i++) {
        float4 w = *reinterpret_cast<const float4*>(&sWT[i][tx * 4]);
        float x0 = xr0[i], x1 = xr1[i], x2 = xr2[i], x3 = xr3[i];
        acc[0][0] = fmaf(x0, w.x, acc[0][0]);
        acc[0][1] = fmaf(x0, w.y, acc[0][1]);
        acc[0][2] = fmaf(x0, w.z, acc[0][2]);
        acc[0][3] = fmaf(x0, w.w, acc[0][3]);
        acc[1][0] = fmaf(x1, w.x, acc[1][0]);
        acc[1][1] = fmaf(x1, w.y, acc[1][1]);
        acc[1][2] = fmaf(x1, w.z, acc[1][2]);
        acc[1][3] = fmaf(x1, w.w, acc[1][3]);
        acc[2][0] = fmaf(x2, w.x, acc[2][0]);
        acc[2][1] = fmaf(x2, w.y, acc[2][1]);
        acc[2][2] = fmaf(x2, w.z, acc[2][2]);
        acc[2][3] = fmaf(x2, w.w, acc[2][3]);
        acc[3][0] = fmaf(x3, w.x, acc[3][0]);
        acc[3][1] = fmaf(x3, w.y, acc[3][1]);
        acc[3][2] = fmaf(x3, w.z, acc[3][2]);
        acc[3][3] = fmaf(x3, w.w, acc[3][3]);
    }

    // ---------------- Epilogue: out = log(acc) + mx -------------------------
    #pragma unroll
    for (int j = 0; j < 4; j++) {
        const int b = b0 + ty * 4 + j;
        float m = sMx[ty * 4 + j];
        float4 o4;
        o4.x = __logf(acc[j][0]) + m;
        o4.y = __logf(acc[j][1]) + m;
        o4.z = __logf(acc[j][2]) + m;
        o4.w = __logf(acc[j][3]) + m;
        *reinterpret_cast<float4*>(
            &out[((size_t)b * PART + p) * ONODES + tx * 4]) = o4;
    }
}

extern "C" void kernel_launch(void* const* d_in, const int* in_sizes, int n_in,
                              void* d_out, int out_size) {
    const float* x      = (const float*)d_in[0];   // [256,128,64]
    const float* weight = (const float*)d_in[1];   // [128,64,64]
    float* out          = (float*)d_out;           // [256,128,64]
    dim3 grid(BATCH / BT, PART);
    sumlayer_kernel<<<grid, NTHREADS>>>(x, weight, out);
}